// round 1
// baseline (speedup 1.0000x reference)
#include <cuda_runtime.h>
#include <math.h>

#define N_SEQ 512          // B*S
#define LEN   128          // L
#define LL2   256          // 2L
#define DM    256          // D_MODEL
#define DT    32           // D_TIME
#define DIN   288          // D_MODEL + D_TIME
#define KE    384          // 3*EMB_DIM
#define ROWS  (N_SEQ*LEN)  // 65536
#define ROWS2 (N_SEQ*LL2)  // 131072

// ---------------- scratch (device globals; no allocation allowed) -----------
__device__ float g_emb[ROWS*KE];        // gathered [subj|obj|rel] embeddings
__device__ float g_x[ROWS*DM];          // enc_input (d<256 part); init = input proj
__device__ float g_tem[ROWS*DT];        // temporal embedding (masked by nonpad)
__device__ float g_cur[2][ROWS*DM];     // per-head residual state
__device__ float g_ci[ROWS2*DIN];       // concat input for QKV projection
__device__ float g_q[ROWS2*DM];
__device__ float g_k[ROWS2*DM];
__device__ float g_v[ROWS2*DM];
__device__ float g_p[N_SEQ*LL2*LL2];    // scores -> probs
__device__ float g_o[ROWS2*DM];         // attention output

// ---------------- small elementwise kernels ---------------------------------
__global__ void k_gather(const int* __restrict__ subj, const int* __restrict__ obj,
                         const int* __restrict__ rel, const float* __restrict__ ent,
                         const float* __restrict__ relw) {
    int i = blockIdx.x * 256 + threadIdx.x;
    if (i >= ROWS * KE) return;
    int row = i / KE;
    int c   = i - row * KE;
    float v;
    if (c < 128)      v = ent[subj[row] * 128 + c];
    else if (c < 256) v = ent[obj[row] * 128 + (c - 128)];
    else              v = relw[rel[row] * 128 + (c - 256)];
    g_emb[i] = v;
}

__global__ void k_tem(const float* __restrict__ time) {
    int i = blockIdx.x * 256 + threadIdx.x;      // over ROWS*16 frequencies
    if (i >= ROWS * 16) return;
    int row = i >> 4;
    int f   = i & 15;
    float t = time[row];
    // div = 10000^(-2f/32)
    float div = expf((float)(2 * f) * -0.28782313662425576f);
    float arg = t * div;
    float np  = (t > 0.f) ? 1.f : 0.f;
    g_tem[row * DT + 2 * f]     = sinf(arg) * np;
    g_tem[row * DT + 2 * f + 1] = cosf(arg) * np;
}

__global__ void k_zero_cur() {
    int i = blockIdx.x * 256 + threadIdx.x;
    if (i < 2 * ROWS * DM) ((float*)g_cur)[i] = 0.f;
}

__global__ void k_build_ci(int h) {
    int i = blockIdx.x * 256 + threadIdx.x;      // over ROWS2*DIN
    if (i >= ROWS2 * DIN) return;
    int n   = i / (LL2 * DIN);
    int rem = i - n * (LL2 * DIN);
    int j   = rem / DIN;
    int d   = rem - j * DIN;
    int jj  = (j < LEN) ? j : j - LEN;
    float v;
    if (d < DM) v = (j < LEN) ? g_x[(n * LEN + j) * DM + d]
                              : g_cur[h][(n * LEN + jj) * DM + d];
    else        v = g_tem[(n * LEN + jj) * DT + (d - DM)];
    g_ci[i] = v;
}

// ---------------- shared SGEMM core (64x64 tile, 4x4 per thread) -------------
__device__ __forceinline__ void mm_load_nn(const float* __restrict__ A, int lda,
                                           const float* __restrict__ B, int ldb,
                                           int m0, int n0, int k0,
                                           float As[16][68], float Bs[16][68]) {
    int tid = threadIdx.x;
    int ar = tid >> 2, ak = (tid & 3) << 2;
    float4 a = *(const float4*)(A + (m0 + ar) * lda + k0 + ak);
    As[ak][ar] = a.x; As[ak + 1][ar] = a.y; As[ak + 2][ar] = a.z; As[ak + 3][ar] = a.w;
    int bk = tid >> 4, bn = (tid & 15) << 2;
    *(float4*)&Bs[bk][bn] = *(const float4*)(B + (k0 + bk) * ldb + n0 + bn);
}

__device__ __forceinline__ void mm_load_nt(const float* __restrict__ A, int lda,
                                           const float* __restrict__ B, int ldb,
                                           int m0, int n0, int k0,
                                           float As[16][68], float Bs[16][68]) {
    int tid = threadIdx.x;
    int ar = tid >> 2, ak = (tid & 3) << 2;
    float4 a = *(const float4*)(A + (m0 + ar) * lda + k0 + ak);
    As[ak][ar] = a.x; As[ak + 1][ar] = a.y; As[ak + 2][ar] = a.z; As[ak + 3][ar] = a.w;
    float4 b = *(const float4*)(B + (n0 + ar) * ldb + k0 + ak);
    Bs[ak][ar] = b.x; Bs[ak + 1][ar] = b.y; Bs[ak + 2][ar] = b.z; Bs[ak + 3][ar] = b.w;
}

__device__ __forceinline__ void mm_fma(const float As[16][68], const float Bs[16][68],
                                       float acc[4][4]) {
    int tx = threadIdx.x & 15, ty = threadIdx.x >> 4;
#pragma unroll
    for (int k = 0; k < 16; k++) {
        float aa[4], bb[4];
        *(float4*)aa = *(const float4*)&As[k][ty << 2];
        *(float4*)bb = *(const float4*)&Bs[k][tx << 2];
#pragma unroll
        for (int i = 0; i < 4; i++)
#pragma unroll
            for (int j = 0; j < 4; j++)
                acc[i][j] += aa[i] * bb[j];
    }
}

// ---------------- GEMM kernels -----------------------------------------------
__global__ __launch_bounds__(256) void k_gemm_x(const float* __restrict__ W,
                                                const float* __restrict__ bias) {
    __shared__ float As[16][68], Bs[16][68];
    float acc[4][4] = {};
    int m0 = blockIdx.y << 6, n0 = blockIdx.x << 6;
    for (int k0 = 0; k0 < KE; k0 += 16) {
        mm_load_nn(g_emb, KE, W, DM, m0, n0, k0, As, Bs);
        __syncthreads();
        mm_fma(As, Bs, acc);
        __syncthreads();
    }
    int tx = threadIdx.x & 15, ty = threadIdx.x >> 4;
#pragma unroll
    for (int i = 0; i < 4; i++) {
        int r = m0 + (ty << 2) + i;
#pragma unroll
        for (int j = 0; j < 4; j++) {
            int c = n0 + (tx << 2) + j;
            g_x[r * DM + c] = acc[i][j] + bias[c];
        }
    }
}

__global__ __launch_bounds__(256) void k_gemm_qkv(
    const float* __restrict__ qw, const float* __restrict__ kw, const float* __restrict__ vw,
    const float* __restrict__ qb, const float* __restrict__ kb, const float* __restrict__ vb,
    int hl) {
    const float* W; const float* bias; float* C;
    if (blockIdx.z == 0)      { W = qw; bias = qb; C = g_q; }
    else if (blockIdx.z == 1) { W = kw; bias = kb; C = g_k; }
    else                      { W = vw; bias = vb; C = g_v; }
    W += hl * DIN * DM;  bias += hl * DM;

    __shared__ float As[16][68], Bs[16][68];
    float acc[4][4] = {};
    int m0 = blockIdx.y << 6, n0 = blockIdx.x << 6;
    for (int k0 = 0; k0 < DIN; k0 += 16) {
        mm_load_nn(g_ci, DIN, W, DM, m0, n0, k0, As, Bs);
        __syncthreads();
        mm_fma(As, Bs, acc);
        __syncthreads();
    }
    int tx = threadIdx.x & 15, ty = threadIdx.x >> 4;
#pragma unroll
    for (int i = 0; i < 4; i++) {
        int r = m0 + (ty << 2) + i;
#pragma unroll
        for (int j = 0; j < 4; j++) {
            int c = n0 + (tx << 2) + j;
            C[r * DM + c] = acc[i][j] + bias[c];
        }
    }
}

__global__ __launch_bounds__(256) void k_scores() {
    int n = blockIdx.z;
    const float* Q  = g_q + n * (LL2 * DM);
    const float* Km = g_k + n * (LL2 * DM);
    float*       P  = g_p + n * (LL2 * LL2);

    __shared__ float As[16][68], Bs[16][68];
    float acc[4][4] = {};
    int m0 = blockIdx.y << 6, n0 = blockIdx.x << 6;
    for (int k0 = 0; k0 < DM; k0 += 16) {
        mm_load_nt(Q, DM, Km, DM, m0, n0, k0, As, Bs);
        __syncthreads();
        mm_fma(As, Bs, acc);
        __syncthreads();
    }
    int tx = threadIdx.x & 15, ty = threadIdx.x >> 4;
#pragma unroll
    for (int i = 0; i < 4; i++) {
        int r = m0 + (ty << 2) + i;
#pragma unroll
        for (int j = 0; j < 4; j++) {
            int c = n0 + (tx << 2) + j;
            P[r * LL2 + c] = acc[i][j] * 0.0625f;  // 1/sqrt(256)
        }
    }
}

__global__ __launch_bounds__(256) void k_pv() {
    int n = blockIdx.z;
    const float* P = g_p + n * (LL2 * LL2);
    const float* V = g_v + n * (LL2 * DM);
    float*       O = g_o + n * (LL2 * DM);

    __shared__ float As[16][68], Bs[16][68];
    float acc[4][4] = {};
    int m0 = blockIdx.y << 6, n0 = blockIdx.x << 6;
    for (int k0 = 0; k0 < LL2; k0 += 16) {
        mm_load_nn(P, LL2, V, DM, m0, n0, k0, As, Bs);
        __syncthreads();
        mm_fma(As, Bs, acc);
        __syncthreads();
    }
    int tx = threadIdx.x & 15, ty = threadIdx.x >> 4;
#pragma unroll
    for (int i = 0; i < 4; i++) {
        int r = m0 + (ty << 2) + i;
#pragma unroll
        for (int j = 0; j < 4; j++) {
            int c = n0 + (tx << 2) + j;
            O[r * DM + c] = acc[i][j];
        }
    }
}

// ---------------- masked softmax (warp per row) ------------------------------
__global__ __launch_bounds__(256) void k_softmax(const float* __restrict__ time) {
    int warp = threadIdx.x >> 5, lane = threadIdx.x & 31;
    int rowId = blockIdx.x * 8 + warp;               // 0 .. N_SEQ*LL2-1
    int n = rowId >> 8;
    int i = rowId & 255;
    float* row = g_p + rowId * LL2;
    const float* tt = time + n * LEN;
    int iq = (i < LEN) ? i : i - LEN;

    float vals[8];
    float mx = -1e30f;
#pragma unroll
    for (int c = 0; c < 8; c++) {
        int j = lane + c * 32;
        float s = row[j];
        bool masked;
        if (j < LEN) masked = (j >= iq) || (tt[j] == 0.f);
        else         masked = !((i >= LEN) && ((j - LEN) == iq));
        s = masked ? -1e9f : s;
        vals[c] = s;
        mx = fmaxf(mx, s);
    }
#pragma unroll
    for (int off = 16; off; off >>= 1) mx = fmaxf(mx, __shfl_xor_sync(0xffffffffu, mx, off));
    float sum = 0.f;
#pragma unroll
    for (int c = 0; c < 8; c++) { vals[c] = expf(vals[c] - mx); sum += vals[c]; }
#pragma unroll
    for (int off = 16; off; off >>= 1) sum += __shfl_xor_sync(0xffffffffu, sum, off);
    float inv = 1.f / sum;
#pragma unroll
    for (int c = 0; c < 8; c++) row[lane + c * 32] = vals[c] * inv;
}

// ---------------- residual update + enc_input refresh ------------------------
__global__ void k_update(const float* __restrict__ time, int h) {
    int i = blockIdx.x * 256 + threadIdx.x;          // over ROWS*DM
    if (i >= ROWS * DM) return;
    int row = i >> 8;                                // n*LEN + l
    int d   = i & 255;
    int n   = row >> 7;
    int l   = row & 127;
    float top = g_o[(n * LL2 + l) * DM + d];
    float bot = g_o[(n * LL2 + LEN + l) * DM + d];
    float np  = (time[row] > 0.f) ? 1.f : 0.f;
    g_cur[h][i] += tanhf(bot * np);
    g_x[i] = top;
}

// ---------------- final MLP head ---------------------------------------------
__global__ __launch_bounds__(256) void k_head(const float* __restrict__ w1,
                                              const float* __restrict__ b1,
                                              const float* __restrict__ w2,
                                              const float* __restrict__ b2,
                                              float* __restrict__ out) {
    int n = blockIdx.x;
    int t = threadIdx.x;
    __shared__ float sl[512];
    __shared__ float sh[256];
    sl[t]       = g_cur[0][(n * LEN + LEN - 1) * DM + t];
    sl[256 + t] = g_cur[1][(n * LEN + LEN - 1) * DM + t];
    __syncthreads();
    float acc = b1[t];
    for (int k = 0; k < 512; k++) acc += sl[k] * w1[k * DM + t];
    float x = acc;
    float g = 0.5f * x * (1.f + erff(x * 0.7071067811865476f));
    sh[t] = g * w2[t];
    __syncthreads();
    for (int s = 128; s > 0; s >>= 1) {
        if (t < s) sh[t] += sh[t + s];
        __syncthreads();
    }
    if (t == 0) out[n] = sh[0] + b2[0];
}

// ---------------- launch ------------------------------------------------------
extern "C" void kernel_launch(void* const* d_in, const int* in_sizes, int n_in,
                              void* d_out, int out_size) {
    const int*   subj = (const int*)d_in[0];
    const int*   obj  = (const int*)d_in[1];
    const int*   rel  = (const int*)d_in[2];
    const float* time = (const float*)d_in[3];
    const float* ent  = (const float*)d_in[4];
    const float* relw = (const float*)d_in[5];
    const float* in_w = (const float*)d_in[6];
    const float* in_b = (const float*)d_in[7];
    const float* q_w  = (const float*)d_in[8];
    const float* q_b  = (const float*)d_in[9];
    const float* k_w  = (const float*)d_in[10];
    const float* k_b  = (const float*)d_in[11];
    const float* v_w  = (const float*)d_in[12];
    const float* v_b  = (const float*)d_in[13];
    const float* w1   = (const float*)d_in[14];
    const float* b1   = (const float*)d_in[15];
    const float* w2   = (const float*)d_in[16];
    const float* b2   = (const float*)d_in[17];
    float* out = (float*)d_out;

    k_gather<<<(ROWS * KE + 255) / 256, 256>>>(subj, obj, rel, ent, relw);
    k_tem<<<(ROWS * 16 + 255) / 256, 256>>>(time);
    k_zero_cur<<<(2 * ROWS * DM + 255) / 256, 256>>>();
    k_gemm_x<<<dim3(DM / 64, ROWS / 64), 256>>>(in_w, in_b);

    for (int h = 0; h < 2; h++) {
        for (int l = 0; l < 2; l++) {
            int hl = h * 2 + l;
            k_build_ci<<<(ROWS2 * DIN + 255) / 256, 256>>>(h);
            k_gemm_qkv<<<dim3(DM / 64, ROWS2 / 64, 3), 256>>>(q_w, k_w, v_w, q_b, k_b, v_b, hl);
            k_scores<<<dim3(LL2 / 64, LL2 / 64, N_SEQ), 256>>>();
            k_softmax<<<(N_SEQ * LL2) / 8, 256>>>(time);
            k_pv<<<dim3(DM / 64, LL2 / 64, N_SEQ), 256>>>();
            k_update<<<(ROWS * DM + 255) / 256, 256>>>(time, h);
        }
    }
    k_head<<<N_SEQ, 256>>>(w1, b1, w2, b2, out);
}

// round 2
// speedup vs baseline: 1.5019x; 1.5019x over previous
#include <cuda_runtime.h>
#include <math.h>

#define N_SEQ 512          // B*S
#define LEN   128          // L
#define LL2   256          // 2L
#define DM    256          // D_MODEL
#define DT    32           // D_TIME
#define DIN   288          // D_MODEL + D_TIME
#define KE    384          // 3*EMB_DIM
#define ROWS  (N_SEQ*LEN)  // 65536
#define ROWS2 (N_SEQ*LL2)  // 131072

// ---------------- scratch (device globals) -----------------------------------
__device__ float g_emb[ROWS*KE];
__device__ float g_x[ROWS*DM];
__device__ float g_tem[ROWS*DT];
__device__ float g_cur[2][ROWS*DM];
__device__ float g_ci[ROWS2*DIN];
__device__ float g_q[ROWS2*DM];
__device__ float g_k[ROWS2*DM];
__device__ float g_v[ROWS2*DM];
__device__ float g_p[N_SEQ*LL2*LEN];    // scores/probs over first-128 keys only
__device__ float g_pd[N_SEQ*LL2];       // diag-prob (bottom rows) / uniform flag (top)
__device__ float g_sv[N_SEQ*DM];        // per-seq sum of V rows 128..255
__device__ float g_o[ROWS2*DM];

// ---------------- small elementwise kernels ----------------------------------
__global__ void k_gather(const int* __restrict__ subj, const int* __restrict__ obj,
                         const int* __restrict__ rel, const float* __restrict__ ent,
                         const float* __restrict__ relw) {
    int i = blockIdx.x * 256 + threadIdx.x;
    if (i >= ROWS * KE) return;
    int row = i / KE;
    int c   = i - row * KE;
    float v;
    if (c < 128)      v = ent[subj[row] * 128 + c];
    else if (c < 256) v = ent[obj[row] * 128 + (c - 128)];
    else              v = relw[rel[row] * 128 + (c - 256)];
    g_emb[i] = v;
}

__global__ void k_tem(const float* __restrict__ time) {
    int i = blockIdx.x * 256 + threadIdx.x;
    if (i >= ROWS * 16) return;
    int row = i >> 4;
    int f   = i & 15;
    float t = time[row];
    float div = expf((float)(2 * f) * -0.28782313662425576f);
    float arg = t * div;
    float np  = (t > 0.f) ? 1.f : 0.f;
    g_tem[row * DT + 2 * f]     = sinf(arg) * np;
    g_tem[row * DT + 2 * f + 1] = cosf(arg) * np;
}

__global__ void k_zero_cur() {
    int i = blockIdx.x * 256 + threadIdx.x;
    if (i < 2 * ROWS * DM) ((float*)g_cur)[i] = 0.f;
}

__global__ void k_build_ci(int h) {
    int i = blockIdx.x * 256 + threadIdx.x;
    if (i >= ROWS2 * DIN) return;
    int n   = i / (LL2 * DIN);
    int rem = i - n * (LL2 * DIN);
    int j   = rem / DIN;
    int d   = rem - j * DIN;
    int jj  = (j < LEN) ? j : j - LEN;
    float v;
    if (d < DM) v = (j < LEN) ? g_x[(n * LEN + j) * DM + d]
                              : g_cur[h][(n * LEN + jj) * DM + d];
    else        v = g_tem[(n * LEN + jj) * DT + (d - DM)];
    g_ci[i] = v;
}

__global__ void k_sv() {   // per-seq column sums of V rows 128..255
    int n = blockIdx.x;
    int d = threadIdx.x;
    const float* vp = g_v + (n * LL2 + LEN) * DM + d;
    float s = 0.f;
#pragma unroll 8
    for (int j = 0; j < LEN; j++) s += vp[j * DM];
    g_sv[n * DM + d] = s;
}

// ---------------- 128x128 SGEMM core (8x8/thread, double-buffered) -----------
__device__ __forceinline__ void gemm_compute(const float (*As)[140], const float (*Bs)[128],
                                             float acc[8][8], int tx, int ty) {
#pragma unroll
    for (int k = 0; k < 8; k++) {
        float a[8], b[8];
        *(float4*)(a)     = *(const float4*)&As[k][ty * 4];
        *(float4*)(a + 4) = *(const float4*)&As[k][64 + ty * 4];
        *(float4*)(b)     = *(const float4*)&Bs[k][tx * 4];
        *(float4*)(b + 4) = *(const float4*)&Bs[k][64 + tx * 4];
#pragma unroll
        for (int i = 0; i < 8; i++)
#pragma unroll
            for (int j = 0; j < 8; j++)
                acc[i][j] += a[i] * b[j];
    }
}

template<bool TB>
__device__ __forceinline__ void run_gemm(const float* __restrict__ A, int lda,
                                         const float* __restrict__ B, int ldb,
                                         int m0, int n0, int Kdim, float acc[8][8]) {
    __shared__ float As[2][8][140];
    __shared__ float Bs[2][8][128];
    int tid = threadIdx.x;
    int tx = tid & 15, ty = tid >> 4;
    int ar = tid >> 1, kg = (tid & 1) << 2;     // A (and NT-B) loader coords
    int br = tid >> 5, bc = (tid & 31) << 2;    // NN-B loader coords

    float4 a = *(const float4*)(A + (m0 + ar) * lda + kg);
    float4 b;
    if (TB) b = *(const float4*)(B + (n0 + ar) * ldb + kg);
    else    b = *(const float4*)(B + br * ldb + n0 + bc);
    As[0][kg][ar] = a.x; As[0][kg + 1][ar] = a.y; As[0][kg + 2][ar] = a.z; As[0][kg + 3][ar] = a.w;
    if (TB) { Bs[0][kg][ar] = b.x; Bs[0][kg + 1][ar] = b.y; Bs[0][kg + 2][ar] = b.z; Bs[0][kg + 3][ar] = b.w; }
    else    *(float4*)&Bs[0][br][bc] = b;
    __syncthreads();

    int buf = 0;
    for (int k0 = 8; k0 < Kdim; k0 += 8) {
        float4 an = *(const float4*)(A + (m0 + ar) * lda + k0 + kg);
        float4 bn;
        if (TB) bn = *(const float4*)(B + (n0 + ar) * ldb + k0 + kg);
        else    bn = *(const float4*)(B + (k0 + br) * ldb + n0 + bc);
        gemm_compute(As[buf], Bs[buf], acc, tx, ty);
        int nb = buf ^ 1;
        As[nb][kg][ar] = an.x; As[nb][kg + 1][ar] = an.y; As[nb][kg + 2][ar] = an.z; As[nb][kg + 3][ar] = an.w;
        if (TB) { Bs[nb][kg][ar] = bn.x; Bs[nb][kg + 1][ar] = bn.y; Bs[nb][kg + 2][ar] = bn.z; Bs[nb][kg + 3][ar] = bn.w; }
        else    *(float4*)&Bs[nb][br][bc] = bn;
        __syncthreads();
        buf = nb;
    }
    gemm_compute(As[buf], Bs[buf], acc, tx, ty);
}

// ---------------- GEMM kernels ------------------------------------------------
__global__ __launch_bounds__(256) void k_gemm_x(const float* __restrict__ W,
                                                const float* __restrict__ bias) {
    float acc[8][8] = {};
    int m0 = blockIdx.y << 7, n0 = blockIdx.x << 7;
    run_gemm<false>(g_emb, KE, W, DM, m0, n0, KE, acc);
    int tx = threadIdx.x & 15, ty = threadIdx.x >> 4;
#pragma unroll
    for (int i = 0; i < 8; i++) {
        int r = m0 + ((i < 4) ? (ty << 2) + i : 64 + (ty << 2) + i - 4);
#pragma unroll
        for (int j = 0; j < 8; j++) {
            int c = n0 + ((j < 4) ? (tx << 2) + j : 64 + (tx << 2) + j - 4);
            g_x[r * DM + c] = acc[i][j] + bias[c];
        }
    }
}

__global__ __launch_bounds__(256) void k_gemm_qkv(
    const float* __restrict__ qw, const float* __restrict__ kw, const float* __restrict__ vw,
    const float* __restrict__ qb, const float* __restrict__ kb, const float* __restrict__ vb,
    int hl) {
    const float* W; const float* bias; float* C;
    if (blockIdx.z == 0)      { W = qw; bias = qb; C = g_q; }
    else if (blockIdx.z == 1) { W = kw; bias = kb; C = g_k; }
    else                      { W = vw; bias = vb; C = g_v; }
    W += hl * DIN * DM;  bias += hl * DM;

    float acc[8][8] = {};
    int m0 = blockIdx.y << 7, n0 = blockIdx.x << 7;
    run_gemm<false>(g_ci, DIN, W, DM, m0, n0, DIN, acc);
    int tx = threadIdx.x & 15, ty = threadIdx.x >> 4;
#pragma unroll
    for (int i = 0; i < 8; i++) {
        int r = m0 + ((i < 4) ? (ty << 2) + i : 64 + (ty << 2) + i - 4);
#pragma unroll
        for (int j = 0; j < 8; j++) {
            int c = n0 + ((j < 4) ? (tx << 2) + j : 64 + (tx << 2) + j - 4);
            C[r * DM + c] = acc[i][j] + bias[c];
        }
    }
}

// scores over first 128 keys only: P[n, i, j] = (Q[n,i] . K[n,j]) / 16, j<128
__global__ __launch_bounds__(256) void k_scores() {
    int n = blockIdx.z;
    const float* Q  = g_q + n * (LL2 * DM);
    const float* Km = g_k + n * (LL2 * DM);
    float*       P  = g_p + n * (LL2 * LEN);

    float acc[8][8] = {};
    int m0 = blockIdx.y << 7, n0 = 0;
    run_gemm<true>(Q, DM, Km, DM, m0, n0, DM, acc);
    int tx = threadIdx.x & 15, ty = threadIdx.x >> 4;
#pragma unroll
    for (int i = 0; i < 8; i++) {
        int r = m0 + ((i < 4) ? (ty << 2) + i : 64 + (ty << 2) + i - 4);
#pragma unroll
        for (int j = 0; j < 8; j++) {
            int c = n0 + ((j < 4) ? (tx << 2) + j : 64 + (tx << 2) + j - 4);
            P[r * LEN + c] = acc[i][j] * 0.0625f;
        }
    }
}

// PV: O = P(:, :128) @ V[:128] + pd * extra   (extra = SV for top, V[r] for bottom)
__global__ __launch_bounds__(256) void k_pv() {
    int n = blockIdx.z;
    const float* P = g_p + n * (LL2 * LEN);
    const float* V = g_v + n * (LL2 * DM);
    float*       O = g_o + n * (LL2 * DM);

    float acc[8][8] = {};
    int m0 = blockIdx.y << 7, n0 = blockIdx.x << 7;
    run_gemm<false>(P, LEN, V, DM, m0, n0, LEN, acc);
    int tx = threadIdx.x & 15, ty = threadIdx.x >> 4;
#pragma unroll
    for (int i = 0; i < 8; i++) {
        int r = m0 + ((i < 4) ? (ty << 2) + i : 64 + (ty << 2) + i - 4);
        float pd = g_pd[n * LL2 + r];
#pragma unroll
        for (int j = 0; j < 8; j++) {
            int c = n0 + ((j < 4) ? (tx << 2) + j : 64 + (tx << 2) + j - 4);
            float extra = (r < LEN) ? g_sv[n * DM + c] : V[r * DM + c];
            O[r * DM + c] = acc[i][j] + pd * extra;
        }
    }
}

// ---------------- masked softmax (warp per row, 128 cols + diag) --------------
__global__ __launch_bounds__(256) void k_softmax(const float* __restrict__ time) {
    int warp = threadIdx.x >> 5, lane = threadIdx.x & 31;
    int rowId = blockIdx.x * 8 + warp;               // 0 .. N_SEQ*LL2-1
    int n = rowId >> 8;
    int i = rowId & 255;
    float* row = g_p + rowId * LEN;
    const float* tt = time + n * LEN;
    bool bottom = (i >= LEN);
    int iq = bottom ? i - LEN : i;

    float vals[4];
    float mx = -1e30f;
#pragma unroll
    for (int c = 0; c < 4; c++) {
        int j = lane + c * 32;
        float s = row[j];
        bool masked = (j >= iq) || (tt[j] == 0.f);
        s = masked ? -1e9f : s;
        vals[c] = s;
        mx = fmaxf(mx, s);
    }

    float d = 0.f;
    if (bottom) {                                    // diag score q_i . k_i / 16
        const float4* qp = (const float4*)(g_q + (n * LL2 + i) * DM);
        const float4* kp = (const float4*)(g_k + (n * LL2 + i) * DM);
#pragma unroll
        for (int c = 0; c < 2; c++) {
            float4 q4 = qp[lane * 2 + c];
            float4 k4 = kp[lane * 2 + c];
            d += q4.x * k4.x + q4.y * k4.y + q4.z * k4.z + q4.w * k4.w;
        }
#pragma unroll
        for (int off = 16; off; off >>= 1) d += __shfl_xor_sync(0xffffffffu, d, off);
        d *= 0.0625f;
    }

#pragma unroll
    for (int off = 16; off; off >>= 1) mx = fmaxf(mx, __shfl_xor_sync(0xffffffffu, mx, off));

    if (!bottom && mx < -5e8f) {
        // fully-masked row: reference softmax is uniform 1/256 over ALL 256 cols
#pragma unroll
        for (int c = 0; c < 4; c++) row[lane + c * 32] = 1.0f / 256.0f;
        if (lane == 0) g_pd[rowId] = 1.0f / 256.0f;  // coefficient on sum(V[128:])
        return;
    }

    if (bottom) mx = fmaxf(mx, d);
    float sum = 0.f;
#pragma unroll
    for (int c = 0; c < 4; c++) { vals[c] = expf(vals[c] - mx); sum += vals[c]; }
#pragma unroll
    for (int off = 16; off; off >>= 1) sum += __shfl_xor_sync(0xffffffffu, sum, off);
    float ed = bottom ? expf(d - mx) : 0.f;
    float inv = 1.f / (sum + ed);
#pragma unroll
    for (int c = 0; c < 4; c++) row[lane + c * 32] = vals[c] * inv;
    if (lane == 0) g_pd[rowId] = ed * inv;           // 0 for normal top rows
}

// ---------------- residual update + enc_input refresh -------------------------
__global__ void k_update(const float* __restrict__ time, int h) {
    int i = blockIdx.x * 256 + threadIdx.x;
    if (i >= ROWS * DM) return;
    int row = i >> 8;
    int d   = i & 255;
    int n   = row >> 7;
    int l   = row & 127;
    float top = g_o[(n * LL2 + l) * DM + d];
    float bot = g_o[(n * LL2 + LEN + l) * DM + d];
    float np  = (time[row] > 0.f) ? 1.f : 0.f;
    g_cur[h][i] += tanhf(bot * np);
    g_x[i] = top;
}

// ---------------- final MLP head ----------------------------------------------
__global__ __launch_bounds__(256) void k_head(const float* __restrict__ w1,
                                              const float* __restrict__ b1,
                                              const float* __restrict__ w2,
                                              const float* __restrict__ b2,
                                              float* __restrict__ out) {
    int n = blockIdx.x;
    int t = threadIdx.x;
    __shared__ float sl[512];
    __shared__ float sh[256];
    sl[t]       = g_cur[0][(n * LEN + LEN - 1) * DM + t];
    sl[256 + t] = g_cur[1][(n * LEN + LEN - 1) * DM + t];
    __syncthreads();
    float acc = b1[t];
    for (int k = 0; k < 512; k++) acc += sl[k] * w1[k * DM + t];
    float x = acc;
    float g = 0.5f * x * (1.f + erff(x * 0.7071067811865476f));
    sh[t] = g * w2[t];
    __syncthreads();
    for (int s = 128; s > 0; s >>= 1) {
        if (t < s) sh[t] += sh[t + s];
        __syncthreads();
    }
    if (t == 0) out[n] = sh[0] + b2[0];
}

// ---------------- launch -------------------------------------------------------
extern "C" void kernel_launch(void* const* d_in, const int* in_sizes, int n_in,
                              void* d_out, int out_size) {
    const int*   subj = (const int*)d_in[0];
    const int*   obj  = (const int*)d_in[1];
    const int*   rel  = (const int*)d_in[2];
    const float* time = (const float*)d_in[3];
    const float* ent  = (const float*)d_in[4];
    const float* relw = (const float*)d_in[5];
    const float* in_w = (const float*)d_in[6];
    const float* in_b = (const float*)d_in[7];
    const float* q_w  = (const float*)d_in[8];
    const float* q_b  = (const float*)d_in[9];
    const float* k_w  = (const float*)d_in[10];
    const float* k_b  = (const float*)d_in[11];
    const float* v_w  = (const float*)d_in[12];
    const float* v_b  = (const float*)d_in[13];
    const float* w1   = (const float*)d_in[14];
    const float* b1   = (const float*)d_in[15];
    const float* w2   = (const float*)d_in[16];
    const float* b2   = (const float*)d_in[17];
    float* out = (float*)d_out;

    k_gather<<<(ROWS * KE + 255) / 256, 256>>>(subj, obj, rel, ent, relw);
    k_tem<<<(ROWS * 16 + 255) / 256, 256>>>(time);
    k_zero_cur<<<(2 * ROWS * DM + 255) / 256, 256>>>();
    k_gemm_x<<<dim3(DM / 128, ROWS / 128), 256>>>(in_w, in_b);

    for (int h = 0; h < 2; h++) {
        for (int l = 0; l < 2; l++) {
            int hl = h * 2 + l;
            k_build_ci<<<(ROWS2 * DIN + 255) / 256, 256>>>(h);
            k_gemm_qkv<<<dim3(DM / 128, ROWS2 / 128, 3), 256>>>(q_w, k_w, v_w, q_b, k_b, v_b, hl);
            k_sv<<<N_SEQ, 256>>>();
            k_scores<<<dim3(1, LL2 / 128, N_SEQ), 256>>>();
            k_softmax<<<(N_SEQ * LL2) / 8, 256>>>(time);
            k_pv<<<dim3(DM / 128, LL2 / 128, N_SEQ), 256>>>();
            k_update<<<(ROWS * DM + 255) / 256, 256>>>(time, h);
        }
    }
    k_head<<<N_SEQ, 256>>>(w1, b1, w2, b2, out);
}

// round 5
// speedup vs baseline: 1.7580x; 1.1706x over previous
#include <cuda_runtime.h>
#include <cuda_bf16.h>
#include <math.h>
#include <stdint.h>

#define N_SEQ 512
#define LEN   128
#define LL2   256
#define DM    256
#define DT    32
#define DIN   288
#define KP    288          // K for QKV mma (multiple of 16)
#define KE    384
#define ROWS  (N_SEQ*LEN)   // 65536
#define ROWS2 (N_SEQ*LL2)   // 131072

// ---------------- scratch ----------------------------------------------------
__device__ float g_emb[ROWS*KE];
__device__ float g_x[ROWS*DM];
__device__ float g_tem[ROWS*DT];
__device__ float g_cur[2][ROWS*DM];
__device__ __nv_bfloat16 g_cih[(size_t)ROWS2*KP];  // ci split-hi
__device__ __nv_bfloat16 g_cil[(size_t)ROWS2*KP];  // ci split-lo
__device__ __nv_bfloat16 g_wTh[3*4*256*KP];        // W^T [z][hl][n][k] hi
__device__ __nv_bfloat16 g_wTl[3*4*256*KP];        // lo
__device__ float g_q[ROWS2*DM];
__device__ float g_k[ROWS2*DM];
__device__ float g_v[ROWS2*DM];
__device__ float g_p[N_SEQ*LL2*LEN];
__device__ float g_pd[N_SEQ*LL2];
__device__ float g_sv[N_SEQ*DM];
__device__ float g_o[ROWS2*DM];

// ---------------- helpers -----------------------------------------------------
__device__ __forceinline__ uint32_t smem_u32(const void* p) {
    uint32_t a;
    asm("{ .reg .u64 t; cvta.to.shared.u64 t, %1; cvt.u32.u64 %0, t; }" : "=r"(a) : "l"(p));
    return a;
}
#define LDSM4(r0, r1, r2, r3, addr) \
    asm volatile("ldmatrix.sync.aligned.m8n8.x4.shared.b16 {%0,%1,%2,%3}, [%4];" \
        : "=r"(r0), "=r"(r1), "=r"(r2), "=r"(r3) : "r"(addr))
#define MMA16816(c, a, b0, b1) \
    asm volatile("mma.sync.aligned.m16n8k16.row.col.f32.bf16.bf16.f32 " \
        "{%0,%1,%2,%3},{%4,%5,%6,%7},{%8,%9},{%0,%1,%2,%3};" \
        : "+f"((c)[0]), "+f"((c)[1]), "+f"((c)[2]), "+f"((c)[3]) \
        : "r"((a)[0]), "r"((a)[1]), "r"((a)[2]), "r"((a)[3]), "r"(b0), "r"(b1))

// ---------------- small elementwise kernels ----------------------------------
__global__ void k_gather(const int* __restrict__ subj, const int* __restrict__ obj,
                         const int* __restrict__ rel, const float* __restrict__ ent,
                         const float* __restrict__ relw) {
    int i = blockIdx.x * 256 + threadIdx.x;
    if (i >= ROWS * KE) return;
    int row = i / KE;
    int c   = i - row * KE;
    float v;
    if (c < 128)      v = ent[subj[row] * 128 + c];
    else if (c < 256) v = ent[obj[row] * 128 + (c - 128)];
    else              v = relw[rel[row] * 128 + (c - 256)];
    g_emb[i] = v;
}

__global__ void k_tem(const float* __restrict__ time) {
    int i = blockIdx.x * 256 + threadIdx.x;
    if (i >= ROWS * 16) return;
    int row = i >> 4;
    int f   = i & 15;
    float t = time[row];
    float div = expf((float)(2 * f) * -0.28782313662425576f);
    float arg = t * div;
    float np  = (t > 0.f) ? 1.f : 0.f;
    g_tem[row * DT + 2 * f]     = sinf(arg) * np;
    g_tem[row * DT + 2 * f + 1] = cosf(arg) * np;
}

__global__ void k_zero_cur() {
    int i = blockIdx.x * 256 + threadIdx.x;
    if (i < 2 * ROWS * DM) ((float*)g_cur)[i] = 0.f;
}

// weight transpose + bf16 split: out[z][hl][n][k] = split(W_z[hl][k][n])
__global__ void k_wconv(const float* __restrict__ qw, const float* __restrict__ kw,
                        const float* __restrict__ vw) {
    int i = blockIdx.x * 256 + threadIdx.x;
    if (i >= 3 * 4 * 256 * KP) return;
    int k  = i % KP;
    int n  = (i / KP) & 255;
    int hl = (i / (KP * 256)) & 3;
    int z  = i / (KP * 256 * 4);
    const float* W = (z == 0) ? qw : (z == 1) ? kw : vw;
    float v = W[(hl * DIN + k) * 256 + n];
    __nv_bfloat16 hi = __float2bfloat16(v);
    __nv_bfloat16 lo = __float2bfloat16(v - __bfloat162float(hi));
    g_wTh[i] = hi;
    g_wTl[i] = lo;
}

// build ci as split-bf16 rows [ROWS2][288]
__global__ void k_build_ci(int h) {
    size_t i = (size_t)blockIdx.x * 256 + threadIdx.x;
    if (i >= (size_t)ROWS2 * KP) return;
    int k   = (int)(i % KP);
    int row = (int)(i / KP);          // n*LL2 + j
    int n   = row >> 8;
    int j   = row & 255;
    int jj  = j & 127;
    float v;
    if (k < DM) v = (j < LEN) ? g_x[(n * LEN + j) * DM + k]
                              : g_cur[h][(n * LEN + jj) * DM + k];
    else        v = g_tem[(n * LEN + jj) * DT + (k - DM)];
    __nv_bfloat16 hi = __float2bfloat16(v);
    __nv_bfloat16 lo = __float2bfloat16(v - __bfloat162float(hi));
    g_cih[i] = hi;
    g_cil[i] = lo;
}

__global__ void k_sv() {
    int n = blockIdx.x;
    int d = threadIdx.x;
    const float* vp = g_v + (n * LL2 + LEN) * DM + d;
    float s = 0.f;
#pragma unroll 8
    for (int j = 0; j < LEN; j++) s += vp[j * DM];
    g_sv[n * DM + d] = s;
}

// ---------------- QKV via mma.sync bf16, 3-term split -------------------------
// grid: x = z*2 + nblk (6), y = m-block (1024). block 256 thr, 8 warps 64x32.
__global__ __launch_bounds__(256) void k_qkv_mma(const float* __restrict__ qb,
                                                 const float* __restrict__ kb,
                                                 const float* __restrict__ vb, int hl) {
    __shared__ __nv_bfloat16 sA[2][128 * 40];
    __shared__ __nv_bfloat16 sB[2][128 * 40];
    int tid = threadIdx.x;
    int z  = blockIdx.x >> 1;
    int n0 = (blockIdx.x & 1) << 7;
    int m0 = blockIdx.y << 7;
    const __nv_bfloat16* Ah = g_cih;
    const __nv_bfloat16* Al = g_cil;
    const __nv_bfloat16* Bh = g_wTh + (size_t)(z * 4 + hl) * 256 * KP;
    const __nv_bfloat16* Bl = g_wTl + (size_t)(z * 4 + hl) * 256 * KP;
    int w = tid >> 5, lane = tid & 31;
    int wm = (w & 1) << 6;            // 0 / 64
    int wn = (w >> 1) << 5;           // 0 / 32 / 64 / 96
    int lr = tid >> 1;                // loader row 0..127
    int lc = (tid & 1) << 1;          // loader chunk pair 0 / 2

    float acc[4][4][4] = {};

    {   // prologue: kt=0 (hi,hi), kk=0
        const uint4* pa = (const uint4*)(Ah + (size_t)(m0 + lr) * KP);
        const uint4* pb = (const uint4*)(Bh + (size_t)(n0 + lr) * KP);
        uint4 a0 = pa[lc], a1 = pa[lc + 1];
        uint4 b0 = pb[lc], b1 = pb[lc + 1];
        *(uint4*)&sA[0][lr * 40 + lc * 8]       = a0;
        *(uint4*)&sA[0][lr * 40 + (lc + 1) * 8] = a1;
        *(uint4*)&sB[0][lr * 40 + lc * 8]       = b0;
        *(uint4*)&sB[0][lr * 40 + (lc + 1) * 8] = b1;
    }
    __syncthreads();

    uint32_t sA0 = smem_u32(&sA[0][0]);
    uint32_t sB0 = smem_u32(&sB[0][0]);
    int buf = 0;

    for (int kt = 0; kt < 27; kt++) {
        uint4 na0, na1, nb0, nb1;
        bool more = (kt < 26);
        if (more) {
            int kt1 = kt + 1;
            int ph  = kt1 / 9;
            int kk  = (kt1 - ph * 9) * 32;
            const __nv_bfloat16* Asrc = (ph == 1) ? Al : Ah;
            const __nv_bfloat16* Bsrc = (ph == 2) ? Bl : Bh;
            const uint4* pa = (const uint4*)(Asrc + (size_t)(m0 + lr) * KP + kk);
            const uint4* pb = (const uint4*)(Bsrc + (size_t)(n0 + lr) * KP + kk);
            na0 = pa[lc]; na1 = pa[lc + 1];
            nb0 = pb[lc]; nb1 = pb[lc + 1];
        }
        uint32_t baseA = sA0 + buf * (128 * 40 * 2);
        uint32_t baseB = sB0 + buf * (128 * 40 * 2);
#pragma unroll
        for (int ks = 0; ks < 2; ks++) {
            uint32_t a[4][4];
#pragma unroll
            for (int mf = 0; mf < 4; mf++) {
                uint32_t addr = baseA + ((wm + mf * 16 + (lane & 15)) * 40
                              + (ks * 2 + ((lane >> 4) & 1)) * 8) * 2;
                LDSM4(a[mf][0], a[mf][1], a[mf][2], a[mf][3], addr);
            }
            uint32_t b[2][4];
#pragma unroll
            for (int p = 0; p < 2; p++) {
                uint32_t addr = baseB + ((wn + p * 16 + (lane & 7) + ((lane >> 4) & 1) * 8) * 40
                              + (ks * 2 + ((lane >> 3) & 1)) * 8) * 2;
                LDSM4(b[p][0], b[p][1], b[p][2], b[p][3], addr);
            }
#pragma unroll
            for (int mf = 0; mf < 4; mf++)
#pragma unroll
                for (int nf = 0; nf < 4; nf++)
                    MMA16816(acc[mf][nf], a[mf], b[nf >> 1][(nf & 1) * 2], b[nf >> 1][(nf & 1) * 2 + 1]);
        }
        if (more) {
            int nb = buf ^ 1;
            *(uint4*)&sA[nb][lr * 40 + lc * 8]       = na0;
            *(uint4*)&sA[nb][lr * 40 + (lc + 1) * 8] = na1;
            *(uint4*)&sB[nb][lr * 40 + lc * 8]       = nb0;
            *(uint4*)&sB[nb][lr * 40 + (lc + 1) * 8] = nb1;
            __syncthreads();
            buf = nb;
        }
    }

    const float* bias = ((z == 0) ? qb : (z == 1) ? kb : vb) + hl * 256;
    float* C = (z == 0) ? g_q : (z == 1) ? g_k : g_v;
    int r0 = lane >> 2, c0 = (lane & 3) << 1;
#pragma unroll
    for (int mf = 0; mf < 4; mf++)
#pragma unroll
        for (int nf = 0; nf < 4; nf++) {
            int row = m0 + wm + mf * 16 + r0;
            int col = n0 + wn + nf * 8 + c0;
            C[(size_t)row * DM + col]           = acc[mf][nf][0] + bias[col];
            C[(size_t)row * DM + col + 1]       = acc[mf][nf][1] + bias[col + 1];
            C[(size_t)(row + 8) * DM + col]     = acc[mf][nf][2] + bias[col];
            C[(size_t)(row + 8) * DM + col + 1] = acc[mf][nf][3] + bias[col + 1];
        }
}

// ---------------- FFMA GEMM core (proven round-2) ------------------------------
__device__ __forceinline__ void gemm_compute(const float (*As)[140], const float (*Bs)[128],
                                             float acc[8][8], int tx, int ty) {
#pragma unroll
    for (int k = 0; k < 8; k++) {
        float a[8], b[8];
        *(float4*)(a)     = *(const float4*)&As[k][ty * 4];
        *(float4*)(a + 4) = *(const float4*)&As[k][64 + ty * 4];
        *(float4*)(b)     = *(const float4*)&Bs[k][tx * 4];
        *(float4*)(b + 4) = *(const float4*)&Bs[k][64 + tx * 4];
#pragma unroll
        for (int i = 0; i < 8; i++)
#pragma unroll
            for (int j = 0; j < 8; j++)
                acc[i][j] += a[i] * b[j];
    }
}

template<bool TB>
__device__ __forceinline__ void run_gemm(const float* __restrict__ A, int lda,
                                         const float* __restrict__ B, int ldb,
                                         int m0, int n0, int Kdim, float acc[8][8]) {
    __shared__ float As[2][8][140];
    __shared__ float Bs[2][8][128];
    int tid = threadIdx.x;
    int tx = tid & 15, ty = tid >> 4;
    int ar = tid >> 1, kg = (tid & 1) << 2;
    int br = tid >> 5, bc = (tid & 31) << 2;

    float4 a = *(const float4*)(A + (m0 + ar) * lda + kg);
    float4 b;
    if (TB) b = *(const float4*)(B + (n0 + ar) * ldb + kg);
    else    b = *(const float4*)(B + br * ldb + n0 + bc);
    As[0][kg][ar] = a.x; As[0][kg + 1][ar] = a.y; As[0][kg + 2][ar] = a.z; As[0][kg + 3][ar] = a.w;
    if (TB) { Bs[0][kg][ar] = b.x; Bs[0][kg + 1][ar] = b.y; Bs[0][kg + 2][ar] = b.z; Bs[0][kg + 3][ar] = b.w; }
    else    *(float4*)&Bs[0][br][bc] = b;
    __syncthreads();

    int buf = 0;
    for (int k0 = 8; k0 < Kdim; k0 += 8) {
        float4 an = *(const float4*)(A + (m0 + ar) * lda + k0 + kg);
        float4 bn;
        if (TB) bn = *(const float4*)(B + (n0 + ar) * ldb + k0 + kg);
        else    bn = *(const float4*)(B + (k0 + br) * ldb + n0 + bc);
        gemm_compute(As[buf], Bs[buf], acc, tx, ty);
        int nb = buf ^ 1;
        As[nb][kg][ar] = an.x; As[nb][kg + 1][ar] = an.y; As[nb][kg + 2][ar] = an.z; As[nb][kg + 3][ar] = an.w;
        if (TB) { Bs[nb][kg][ar] = bn.x; Bs[nb][kg + 1][ar] = bn.y; Bs[nb][kg + 2][ar] = bn.z; Bs[nb][kg + 3][ar] = bn.w; }
        else    *(float4*)&Bs[nb][br][bc] = bn;
        __syncthreads();
        buf = nb;
    }
    gemm_compute(As[buf], Bs[buf], acc, tx, ty);
}

__global__ __launch_bounds__(256) void k_gemm_x(const float* __restrict__ W,
                                                const float* __restrict__ bias) {
    float acc[8][8] = {};
    int m0 = blockIdx.y << 7, n0 = blockIdx.x << 7;
    run_gemm<false>(g_emb, KE, W, DM, m0, n0, KE, acc);
    int tx = threadIdx.x & 15, ty = threadIdx.x >> 4;
#pragma unroll
    for (int i = 0; i < 8; i++) {
        int r = m0 + ((i < 4) ? (ty << 2) + i : 64 + (ty << 2) + i - 4);
#pragma unroll
        for (int j = 0; j < 8; j++) {
            int c = n0 + ((j < 4) ? (tx << 2) + j : 64 + (tx << 2) + j - 4);
            g_x[r * DM + c] = acc[i][j] + bias[c];
        }
    }
}

__global__ __launch_bounds__(256) void k_scores() {
    int n = blockIdx.z;
    const float* Q  = g_q + n * (LL2 * DM);
    const float* Km = g_k + n * (LL2 * DM);
    float*       P  = g_p + n * (LL2 * LEN);
    float acc[8][8] = {};
    int m0 = blockIdx.y << 7, n0 = 0;
    run_gemm<true>(Q, DM, Km, DM, m0, n0, DM, acc);
    int tx = threadIdx.x & 15, ty = threadIdx.x >> 4;
#pragma unroll
    for (int i = 0; i < 8; i++) {
        int r = m0 + ((i < 4) ? (ty << 2) + i : 64 + (ty << 2) + i - 4);
#pragma unroll
        for (int j = 0; j < 8; j++) {
            int c = n0 + ((j < 4) ? (tx << 2) + j : 64 + (tx << 2) + j - 4);
            P[r * LEN + c] = acc[i][j] * 0.0625f;
        }
    }
}

__global__ __launch_bounds__(256) void k_pv() {
    int n = blockIdx.z;
    const float* P = g_p + n * (LL2 * LEN);
    const float* V = g_v + n * (LL2 * DM);
    float*       O = g_o + n * (LL2 * DM);
    float acc[8][8] = {};
    int m0 = blockIdx.y << 7, n0 = blockIdx.x << 7;
    run_gemm<false>(P, LEN, V, DM, m0, n0, LEN, acc);
    int tx = threadIdx.x & 15, ty = threadIdx.x >> 4;
#pragma unroll
    for (int i = 0; i < 8; i++) {
        int r = m0 + ((i < 4) ? (ty << 2) + i : 64 + (ty << 2) + i - 4);
        float pd = g_pd[n * LL2 + r];
#pragma unroll
        for (int j = 0; j < 8; j++) {
            int c = n0 + ((j < 4) ? (tx << 2) + j : 64 + (tx << 2) + j - 4);
            float extra = (r < LEN) ? g_sv[n * DM + c] : V[r * DM + c];
            O[r * DM + c] = acc[i][j] + pd * extra;
        }
    }
}

__global__ __launch_bounds__(256) void k_softmax(const float* __restrict__ time) {
    int warp = threadIdx.x >> 5, lane = threadIdx.x & 31;
    int rowId = blockIdx.x * 8 + warp;
    int n = rowId >> 8;
    int i = rowId & 255;
    float* row = g_p + rowId * LEN;
    const float* tt = time + n * LEN;
    bool bottom = (i >= LEN);
    int iq = bottom ? i - LEN : i;

    float vals[4];
    float mx = -1e30f;
#pragma unroll
    for (int c = 0; c < 4; c++) {
        int j = lane + c * 32;
        float s = row[j];
        bool masked = (j >= iq) || (tt[j] == 0.f);
        s = masked ? -1e9f : s;
        vals[c] = s;
        mx = fmaxf(mx, s);
    }
    float d = 0.f;
    if (bottom) {
        const float4* qp = (const float4*)(g_q + (size_t)(n * LL2 + i) * DM);
        const float4* kp = (const float4*)(g_k + (size_t)(n * LL2 + i) * DM);
#pragma unroll
        for (int c = 0; c < 2; c++) {
            float4 q4 = qp[lane * 2 + c];
            float4 k4 = kp[lane * 2 + c];
            d += q4.x * k4.x + q4.y * k4.y + q4.z * k4.z + q4.w * k4.w;
        }
#pragma unroll
        for (int off = 16; off; off >>= 1) d += __shfl_xor_sync(0xffffffffu, d, off);
        d *= 0.0625f;
    }
#pragma unroll
    for (int off = 16; off; off >>= 1) mx = fmaxf(mx, __shfl_xor_sync(0xffffffffu, mx, off));

    if (!bottom && mx < -5e8f) {
#pragma unroll
        for (int c = 0; c < 4; c++) row[lane + c * 32] = 1.0f / 256.0f;
        if (lane == 0) g_pd[rowId] = 1.0f / 256.0f;
        return;
    }
    if (bottom) mx = fmaxf(mx, d);
    float sum = 0.f;
#pragma unroll
    for (int c = 0; c < 4; c++) { vals[c] = expf(vals[c] - mx); sum += vals[c]; }
#pragma unroll
    for (int off = 16; off; off >>= 1) sum += __shfl_xor_sync(0xffffffffu, sum, off);
    float ed = bottom ? expf(d - mx) : 0.f;
    float inv = 1.f / (sum + ed);
#pragma unroll
    for (int c = 0; c < 4; c++) row[lane + c * 32] = vals[c] * inv;
    if (lane == 0) g_pd[rowId] = ed * inv;
}

__global__ void k_update(const float* __restrict__ time, int h) {
    int i = blockIdx.x * 256 + threadIdx.x;
    if (i >= ROWS * DM) return;
    int row = i >> 8;
    int d   = i & 255;
    int n   = row >> 7;
    int l   = row & 127;
    float top = g_o[(n * LL2 + l) * DM + d];
    float bot = g_o[(n * LL2 + LEN + l) * DM + d];
    float np  = (time[row] > 0.f) ? 1.f : 0.f;
    g_cur[h][i] += tanhf(bot * np);
    g_x[i] = top;
}

__global__ __launch_bounds__(256) void k_head(const float* __restrict__ w1,
                                              const float* __restrict__ b1,
                                              const float* __restrict__ w2,
                                              const float* __restrict__ b2,
                                              float* __restrict__ out) {
    int n = blockIdx.x;
    int t = threadIdx.x;
    __shared__ float sl[512];
    __shared__ float sh[256];
    sl[t]       = g_cur[0][(n * LEN + LEN - 1) * DM + t];
    sl[256 + t] = g_cur[1][(n * LEN + LEN - 1) * DM + t];
    __syncthreads();
    float acc = b1[t];
    for (int k = 0; k < 512; k++) acc += sl[k] * w1[k * DM + t];
    float x = acc;
    float g = 0.5f * x * (1.f + erff(x * 0.7071067811865476f));
    sh[t] = g * w2[t];
    __syncthreads();
    for (int s = 128; s > 0; s >>= 1) {
        if (t < s) sh[t] += sh[t + s];
        __syncthreads();
    }
    if (t == 0) out[n] = sh[0] + b2[0];
}

// ---------------- launch ------------------------------------------------------
extern "C" void kernel_launch(void* const* d_in, const int* in_sizes, int n_in,
                              void* d_out, int out_size) {
    const int*   subj = (const int*)d_in[0];
    const int*   obj  = (const int*)d_in[1];
    const int*   rel  = (const int*)d_in[2];
    const float* time = (const float*)d_in[3];
    const float* ent  = (const float*)d_in[4];
    const float* relw = (const float*)d_in[5];
    const float* in_w = (const float*)d_in[6];
    const float* in_b = (const float*)d_in[7];
    const float* q_w  = (const float*)d_in[8];
    const float* q_b  = (const float*)d_in[9];
    const float* k_w  = (const float*)d_in[10];
    const float* k_b  = (const float*)d_in[11];
    const float* v_w  = (const float*)d_in[12];
    const float* v_b  = (const float*)d_in[13];
    const float* w1   = (const float*)d_in[14];
    const float* b1   = (const float*)d_in[15];
    const float* w2   = (const float*)d_in[16];
    const float* b2   = (const float*)d_in[17];
    float* out = (float*)d_out;

    k_gather<<<(ROWS * KE + 255) / 256, 256>>>(subj, obj, rel, ent, relw);
    k_tem<<<(ROWS * 16 + 255) / 256, 256>>>(time);
    k_zero_cur<<<(2 * ROWS * DM + 255) / 256, 256>>>();
    k_wconv<<<(3 * 4 * 256 * KP + 255) / 256, 256>>>(q_w, k_w, v_w);
    k_gemm_x<<<dim3(DM / 128, ROWS / 128), 256>>>(in_w, in_b);

    for (int h = 0; h < 2; h++) {
        for (int l = 0; l < 2; l++) {
            int hl = h * 2 + l;
            k_build_ci<<<(int)(((size_t)ROWS2 * KP + 255) / 256), 256>>>(h);
            k_qkv_mma<<<dim3(6, ROWS2 / 128), 256>>>(q_b, k_b, v_b, hl);
            k_sv<<<N_SEQ, 256>>>();
            k_scores<<<dim3(1, LL2 / 128, N_SEQ), 256>>>();
            k_softmax<<<(N_SEQ * LL2) / 8, 256>>>(time);
            k_pv<<<dim3(DM / 128, LL2 / 128, N_SEQ), 256>>>();
            k_update<<<(ROWS * DM + 255) / 256, 256>>>(time, h);
        }
    }
    k_head<<<N_SEQ, 256>>>(w1, b1, w2, b2, out);
}